// round 14
// baseline (speedup 1.0000x reference)
#include <cuda_runtime.h>
#include <cuda_fp16.h>
#include <cstdint>

// channel_attention collapses to: out = LN_c(Wp @ x + bp)*gp + betap + x
// (softmax row-sum == 1 makes the q/k/attention branch an identity).
//
// HMMA m16n8k16 fp16 GEMM (y = Wh*Xh; rel_err ~2.5e-4 incl. fp16 residual).
// A fragments STREAMED from an L1-hot pre-packed global image (registers
// can't hold W at the 2-CTA/SM 128-reg cap -- r7/r13 both spilled).
// X: LDG float4 -> fp16 regs -> STS, double-buffered XH, prefetch at
// iteration end. LN combine via transposed red[col][jg] + LDS.128, mu/rs
// just-in-time. 2 syncs/tile. 8 warps = 4 j-groups x 2 s-halves.

#define C        128
#define S        400
#define TS       80
#define NTILES   5
#define THREADS  256
#define XPITCH   88                     // fp16 pitch (halves)
#define KSTEP    (16 * XPITCH * 2)

#define SM_XH0   0                      // 128*88*2 = 22528
#define SM_XH1   32768
#define SM_BP    55296
#define SM_GP    (SM_BP + 512)
#define SM_BT    (SM_GP + 512)
#define SM_RED   (SM_BT + 512)          // float2[80 cols][4 jg] = 2560
#define SM_TOTAL (SM_RED + 2560)        // 59392 B

// Wh fragments in mma order: [mt 8][ks 8][lane 32] x uint4 (16 KB, L1-hot)
__device__ __align__(16) uint32_t Whf[8 * 8 * 32 * 4];

__device__ __forceinline__ uint32_t smem_u32(const void* p) {
    uint32_t a;
    asm("{ .reg .u64 t; cvta.to.shared.u64 t, %1; cvt.u32.u64 %0, t; }"
        : "=r"(a) : "l"(p));
    return a;
}
__device__ __forceinline__ void ldsm4t(uint32_t* r, uint32_t addr) {
    asm volatile("ldmatrix.sync.aligned.m8n8.x4.trans.shared.b16 {%0,%1,%2,%3}, [%4];"
                 : "=r"(r[0]), "=r"(r[1]), "=r"(r[2]), "=r"(r[3]) : "r"(addr));
}
__device__ __forceinline__ void ldsm2t(uint32_t* r, uint32_t addr) {
    asm volatile("ldmatrix.sync.aligned.m8n8.x2.trans.shared.b16 {%0,%1}, [%2];"
                 : "=r"(r[0]), "=r"(r[1]) : "r"(addr));
}
__device__ __forceinline__ void mma16816(float d[4], uint4 a,
                                         uint32_t b0, uint32_t b1) {
    asm volatile(
        "mma.sync.aligned.m16n8k16.row.col.f32.f16.f16.f32 "
        "{%0,%1,%2,%3}, {%4,%5,%6,%7}, {%8,%9}, {%0,%1,%2,%3};"
        : "+f"(d[0]), "+f"(d[1]), "+f"(d[2]), "+f"(d[3])
        : "r"(a.x), "r"(a.y), "r"(a.z), "r"(a.w), "r"(b0), "r"(b1));
}
__device__ __forceinline__ uint32_t pk_h2(float a, float b) {
    __half2 h = __floats2half2_rn(a, b);    // low = a
    return *reinterpret_cast<uint32_t*>(&h);
}

// pack Wh into mma A-fragment order (mt = 16-j tile index 0..7)
__global__ void wprep(const float* __restrict__ Wp) {
    int idx  = blockIdx.x * 256 + threadIdx.x;   // (mt*8+ks)*32+lane
    int lane = idx & 31;
    int ks   = (idx >> 5) & 7;
    int mt   = idx >> 8;
    uint32_t h4[4];
    #pragma unroll
    for (int r = 0; r < 4; r++) {
        int j = mt * 16 + (r & 1) * 8 + (lane >> 2);
        int c = ks * 16 + (r >> 1) * 8 + 2 * (lane & 3);
        h4[r] = pk_h2(Wp[j * C + c], Wp[j * C + c + 1]);
    }
    ((uint4*)Whf)[idx] = make_uint4(h4[0], h4[1], h4[2], h4[3]);
}

extern __shared__ char smem[];

__device__ __forceinline__ void load_pre(uint2 pre[10], int tid,
                                         const float* __restrict__ xt) {
    #pragma unroll
    for (int k = 0; k < 10; k++) {
        int idx = tid + k * THREADS;
        int c = idx / 20;
        int q = (idx % 20) * 4;
        float4 v = __ldg((const float4*)(xt + (size_t)c * S + q));
        pre[k] = make_uint2(pk_h2(v.x, v.y), pk_h2(v.z, v.w));
    }
}

__global__ __launch_bounds__(THREADS, 2)
void ca_mma(const float* __restrict__ x,
            const float* __restrict__ bp,
            const float* __restrict__ gp,
            const float* __restrict__ betap,
            float* __restrict__ out) {
    const int tid  = threadIdx.x;
    const int warp = tid >> 5;
    const int lane = tid & 31;
    const int jg   = warp >> 1;          // 0..3 : 32-j group
    const int sh   = warp & 1;           // 0..1 : 40-s half
    const int g    = lane >> 2;
    const int t4   = lane & 3;
    const int bo   = blockIdx.x;

    const float* xg = x   + (size_t)bo * C * S;
    float*       ob = out + (size_t)bo * C * S;

    float*  sbp = (float*)(smem + SM_BP);
    float*  sgp = (float*)(smem + SM_GP);
    float*  sbt = (float*)(smem + SM_BT);
    float2* red = (float2*)(smem + SM_RED);   // [col][jg]

    if (tid < C) {
        sbp[tid] = bp[tid];
        sgp[tid] = gp[tid];
        sbt[tid] = betap[tid];
    }

    const int lr = lane & 15;
    const int lc = (lane >> 4) << 3;
    const int sb = sh * 40;
    const uint32_t s0   = smem_u32(smem);
    const uint32_t xrel = (uint32_t)((lr * XPITCH + sb + lc) * 2);
    const uint4* wh = (const uint4*)Whf;

    // prefetch+convert tile 0
    uint2 pre[10];
    load_pre(pre, tid, xg);

    for (int t = 0; t < NTILES; t++) {
        const uint32_t xhb = (t & 1) ? SM_XH1 : SM_XH0;
        __half* xh = (__half*)(smem + xhb);

        // store converted tile (race-free by barrier ordering: readers of
        // this buffer finished >= 2 barriers ago)
        #pragma unroll
        for (int k = 0; k < 10; k++) {
            int idx = tid + k * THREADS;
            int c = idx / 20;
            int q = (idx % 20) * 4;
            *(uint2*)(xh + c * XPITCH + q) = pre[k];
        }
        __syncthreads();

        // ---- MMA: A streamed from global (L1-hot), B via ldsm ----
        const uint32_t aXh = s0 + xhb + xrel;
        float d[2][5][4];
        #pragma unroll
        for (int mt = 0; mt < 2; mt++)
            #pragma unroll
            for (int n = 0; n < 5; n++)
                #pragma unroll
                for (int i = 0; i < 4; i++) d[mt][n][i] = 0.0f;

        #pragma unroll
        for (int ks = 0; ks < 8; ks++) {
            uint4 ah0 = __ldg(wh + ((2 * jg)     * 8 + ks) * 32 + lane);
            uint4 ah1 = __ldg(wh + ((2 * jg + 1) * 8 + ks) * 32 + lane);
            uint32_t bh[10];
            ldsm4t(bh,     aXh + ks * KSTEP);
            ldsm4t(bh + 4, aXh + ks * KSTEP + 32);
            ldsm2t(bh + 8, aXh + ks * KSTEP + 64);
            #pragma unroll
            for (int n = 0; n < 5; n++) {
                mma16816(d[0][n], ah0, bh[2 * n], bh[2 * n + 1]);
                mma16816(d[1][n], ah1, bh[2 * n], bh[2 * n + 1]);
            }
        }

        // ---- +bias, LN partials over 32 j in-warp ----
        float sum[5][2], sq[5][2];
        #pragma unroll
        for (int n = 0; n < 5; n++)
            #pragma unroll
            for (int p = 0; p < 2; p++) { sum[n][p] = 0.f; sq[n][p] = 0.f; }

        #pragma unroll
        for (int mt = 0; mt < 2; mt++) {
            int j0 = jg * 32 + mt * 16 + g;
            float b0 = sbp[j0], b1 = sbp[j0 + 8];
            #pragma unroll
            for (int n = 0; n < 5; n++) {
                d[mt][n][0] += b0;
                d[mt][n][1] += b0;
                d[mt][n][2] += b1;
                d[mt][n][3] += b1;
                sum[n][0] += d[mt][n][0] + d[mt][n][2];
                sum[n][1] += d[mt][n][1] + d[mt][n][3];
                sq[n][0] = fmaf(d[mt][n][0], d[mt][n][0],
                           fmaf(d[mt][n][2], d[mt][n][2], sq[n][0]));
                sq[n][1] = fmaf(d[mt][n][1], d[mt][n][1],
                           fmaf(d[mt][n][3], d[mt][n][3], sq[n][1]));
            }
        }
        #pragma unroll
        for (int off = 4; off <= 16; off <<= 1) {
            #pragma unroll
            for (int n = 0; n < 5; n++) {
                #pragma unroll
                for (int p = 0; p < 2; p++) {
                    sum[n][p] += __shfl_xor_sync(0xffffffffu, sum[n][p], off);
                    sq[n][p]  += __shfl_xor_sync(0xffffffffu, sq[n][p],  off);
                }
            }
        }
        if (lane < 4) {   // writer lane == t4, g==0
            #pragma unroll
            for (int n = 0; n < 5; n++)
                #pragma unroll
                for (int p = 0; p < 2; p++)
                    red[(sb + n * 8 + 2 * lane + p) * 4 + jg] =
                        make_float2(sum[n][p], sq[n][p]);
        }
        __syncthreads();

        // ---- apply: mu/rs just-in-time via LDS.128, residual from fp16 ----
        const int tb = t * TS;
        #pragma unroll
        for (int n = 0; n < 5; n++) {
            float mu[2], rs[2];
            #pragma unroll
            for (int p = 0; p < 2; p++) {
                int col = sb + n * 8 + 2 * t4 + p;
                const float4* q = (const float4*)(red + col * 4);
                float4 a = q[0], b = q[1];
                float sv = (a.x + a.z) + (b.x + b.z);
                float qv = (a.y + a.w) + (b.y + b.w);
                float m_ = sv * (1.0f / 128.0f);
                mu[p] = m_;
                rs[p] = rsqrtf(qv * (1.0f / 128.0f) - m_ * m_);
            }
            int sl = sb + n * 8 + 2 * t4;
            #pragma unroll
            for (int mt = 0; mt < 2; mt++) {
                int j0 = jg * 32 + mt * 16 + g;
                int j1 = j0 + 8;
                float g0 = sgp[j0], e0 = sbt[j0];
                float g1 = sgp[j1], e1 = sbt[j1];
                __half2 x0 = *(__half2*)(xh + j0 * XPITCH + sl);
                __half2 x1 = *(__half2*)(xh + j1 * XPITCH + sl);
                float2 o0, o1;
                o0.x = (d[mt][n][0] - mu[0]) * rs[0] * g0 + e0 +
                       __half2float(x0.x);
                o0.y = (d[mt][n][1] - mu[1]) * rs[1] * g0 + e0 +
                       __half2float(x0.y);
                o1.x = (d[mt][n][2] - mu[0]) * rs[0] * g1 + e1 +
                       __half2float(x1.x);
                o1.y = (d[mt][n][3] - mu[1]) * rs[1] * g1 + e1 +
                       __half2float(x1.y);
                *(float2*)(ob + (size_t)j0 * S + tb + sl) = o0;
                *(float2*)(ob + (size_t)j1 * S + tb + sl) = o1;
            }
        }

        // prefetch next tile (short live range: here -> next STS)
        if (t + 1 < NTILES)
            load_pre(pre, tid, xg + (t + 1) * TS);
    }
}

extern "C" void kernel_launch(void* const* d_in, const int* in_sizes, int n_in,
                              void* d_out, int out_size) {
    // metadata order: x, Wq, bq, gq, betaq, Wk, bk, gk, betak, Wp, bp, gp, betap
    const float* x     = (const float*)d_in[0];
    const float* Wp    = (const float*)d_in[9];
    const float* bp    = (const float*)d_in[10];
    const float* gp    = (const float*)d_in[11];
    const float* betap = (const float*)d_in[12];
    float* out = (float*)d_out;

    const int BO = in_sizes[0] / (C * S);   // 1024

    cudaFuncSetAttribute(ca_mma, cudaFuncAttributeMaxDynamicSharedMemorySize,
                         SM_TOTAL);

    wprep<<<8, 256>>>(Wp);
    ca_mma<<<BO, THREADS, SM_TOTAL>>>(x, bp, gp, betap, out);
}

// round 15
// speedup vs baseline: 1.1446x; 1.1446x over previous
#include <cuda_runtime.h>
#include <cuda_fp16.h>
#include <cstdint>

// channel_attention collapses to: out = LN_c(Wp @ x + bp)*gp + betap + x
// (softmax row-sum == 1 makes the q/k/attention branch an identity).
//
// Round-12 structure (proven 128us) + ONE change: transposed red[col][jg]
// so the LN 4-group combine is 2x LDS.128 instead of 4x LDS.64 per (n,p),
// with mu/rs still computed BATCHED (rsqrtf ILP preserved).
//
// HMMA m16n8k16 fp16 GEMM (y = Wh*Xh; rel_err ~2.5e-4 incl. fp16 residual).
// X: LDG float4 -> fp16 regs -> STS, double-buffered XH; prefetch overlaps
// MMA (round-12 position). A streamed from L1-hot pre-packed global image.
// 8 warps = 4 j-groups x 2 s-halves; ~58 KB smem, 2 CTAs/SM.

#define C        128
#define S        400
#define TS       80
#define NTILES   5
#define THREADS  256
#define XPITCH   88                     // fp16 pitch (halves)
#define KSTEP    (16 * XPITCH * 2)

#define SM_XH0   0                      // 128*88*2 = 22528
#define SM_XH1   32768
#define SM_BP    55296
#define SM_GP    (SM_BP + 512)
#define SM_BT    (SM_GP + 512)
#define SM_RED   (SM_BT + 512)          // float2[80 cols][4 jg] = 2560
#define SM_TOTAL (SM_RED + 2560)        // 59392 B

// Wh fragments in mma order: [mt 8][ks 8][lane 32] x uint4 (16 KB, L1-hot)
__device__ __align__(16) uint32_t Whf[8 * 8 * 32 * 4];

__device__ __forceinline__ uint32_t smem_u32(const void* p) {
    uint32_t a;
    asm("{ .reg .u64 t; cvta.to.shared.u64 t, %1; cvt.u32.u64 %0, t; }"
        : "=r"(a) : "l"(p));
    return a;
}
__device__ __forceinline__ void ldsm4t(uint32_t* r, uint32_t addr) {
    asm volatile("ldmatrix.sync.aligned.m8n8.x4.trans.shared.b16 {%0,%1,%2,%3}, [%4];"
                 : "=r"(r[0]), "=r"(r[1]), "=r"(r[2]), "=r"(r[3]) : "r"(addr));
}
__device__ __forceinline__ void ldsm2t(uint32_t* r, uint32_t addr) {
    asm volatile("ldmatrix.sync.aligned.m8n8.x2.trans.shared.b16 {%0,%1}, [%2];"
                 : "=r"(r[0]), "=r"(r[1]) : "r"(addr));
}
__device__ __forceinline__ void mma16816(float d[4], uint4 a,
                                         uint32_t b0, uint32_t b1) {
    asm volatile(
        "mma.sync.aligned.m16n8k16.row.col.f32.f16.f16.f32 "
        "{%0,%1,%2,%3}, {%4,%5,%6,%7}, {%8,%9}, {%0,%1,%2,%3};"
        : "+f"(d[0]), "+f"(d[1]), "+f"(d[2]), "+f"(d[3])
        : "r"(a.x), "r"(a.y), "r"(a.z), "r"(a.w), "r"(b0), "r"(b1));
}
__device__ __forceinline__ uint32_t pk_h2(float a, float b) {
    __half2 h = __floats2half2_rn(a, b);    // low = a
    return *reinterpret_cast<uint32_t*>(&h);
}

// pack Wh into mma A-fragment order (mt = 16-j tile index 0..7)
__global__ void wprep(const float* __restrict__ Wp) {
    int idx  = blockIdx.x * 256 + threadIdx.x;   // (mt*8+ks)*32+lane
    int lane = idx & 31;
    int ks   = (idx >> 5) & 7;
    int mt   = idx >> 8;
    uint32_t h4[4];
    #pragma unroll
    for (int r = 0; r < 4; r++) {
        int j = mt * 16 + (r & 1) * 8 + (lane >> 2);
        int c = ks * 16 + (r >> 1) * 8 + 2 * (lane & 3);
        h4[r] = pk_h2(Wp[j * C + c], Wp[j * C + c + 1]);
    }
    ((uint4*)Whf)[idx] = make_uint4(h4[0], h4[1], h4[2], h4[3]);
}

extern __shared__ char smem[];

// load one 80-s tile slice into fp16 register chunks (10 x uint2 / thread)
__device__ __forceinline__ void load_pre(uint2 pre[10], int tid,
                                         const float* __restrict__ xt) {
    #pragma unroll
    for (int k = 0; k < 10; k++) {
        int idx = tid + k * THREADS;
        int c = idx / 20;
        int q = (idx % 20) * 4;
        float4 v = __ldg((const float4*)(xt + (size_t)c * S + q));
        pre[k] = make_uint2(pk_h2(v.x, v.y), pk_h2(v.z, v.w));
    }
}

__global__ __launch_bounds__(THREADS, 2)
void ca_mma(const float* __restrict__ x,
            const float* __restrict__ bp,
            const float* __restrict__ gp,
            const float* __restrict__ betap,
            float* __restrict__ out) {
    const int tid  = threadIdx.x;
    const int warp = tid >> 5;
    const int lane = tid & 31;
    const int jg   = warp >> 1;          // 0..3 : 32-j group
    const int sh   = warp & 1;           // 0..1 : 40-s half
    const int g    = lane >> 2;
    const int t4   = lane & 3;
    const int bo   = blockIdx.x;

    const float* xg = x   + (size_t)bo * C * S;
    float*       ob = out + (size_t)bo * C * S;

    float*  sbp = (float*)(smem + SM_BP);
    float*  sgp = (float*)(smem + SM_GP);
    float*  sbt = (float*)(smem + SM_BT);
    float2* red = (float2*)(smem + SM_RED);   // [col][jg]

    if (tid < C) {
        sbp[tid] = bp[tid];
        sgp[tid] = gp[tid];
        sbt[tid] = betap[tid];
    }

    const int lr = lane & 15;
    const int lc = (lane >> 4) << 3;
    const int sb = sh * 40;
    const uint32_t s0   = smem_u32(smem);
    const uint32_t xrel = (uint32_t)((lr * XPITCH + sb + lc) * 2);
    const uint4* wh = (const uint4*)Whf;

    // prefetch+convert tile 0 into registers
    uint2 pre[10];
    load_pre(pre, tid, xg);

    for (int t = 0; t < NTILES; t++) {
        const uint32_t xhb = (t & 1) ? SM_XH1 : SM_XH0;
        __half* xh = (__half*)(smem + xhb);

        __syncthreads();   // XH(t&1) readers (tile t-2) are done
        // store converted tile, then issue next tile's loads (r12 position)
        #pragma unroll
        for (int k = 0; k < 10; k++) {
            int idx = tid + k * THREADS;
            int c = idx / 20;
            int q = (idx % 20) * 4;
            *(uint2*)(xh + c * XPITCH + q) = pre[k];
        }
        if (t + 1 < NTILES)
            load_pre(pre, tid, xg + (t + 1) * TS);
        __syncthreads();

        // ---- MMA: A streamed from global (L1-hot), B via ldsm ----
        const uint32_t aXh = s0 + xhb + xrel;
        float d[2][5][4];
        #pragma unroll
        for (int mt = 0; mt < 2; mt++)
            #pragma unroll
            for (int n = 0; n < 5; n++)
                #pragma unroll
                for (int i = 0; i < 4; i++) d[mt][n][i] = 0.0f;

        #pragma unroll
        for (int ks = 0; ks < 8; ks++) {
            uint4 ah0 = __ldg(wh + ((2 * jg)     * 8 + ks) * 32 + lane);
            uint4 ah1 = __ldg(wh + ((2 * jg + 1) * 8 + ks) * 32 + lane);
            uint32_t bh[10];
            ldsm4t(bh,     aXh + ks * KSTEP);
            ldsm4t(bh + 4, aXh + ks * KSTEP + 32);
            ldsm2t(bh + 8, aXh + ks * KSTEP + 64);
            #pragma unroll
            for (int n = 0; n < 5; n++) {
                mma16816(d[0][n], ah0, bh[2 * n], bh[2 * n + 1]);
                mma16816(d[1][n], ah1, bh[2 * n], bh[2 * n + 1]);
            }
        }

        // ---- epilogue: +bias, LN stats over 32 j in-warp ----
        float sum[5][2], sq[5][2];
        #pragma unroll
        for (int n = 0; n < 5; n++)
            #pragma unroll
            for (int p = 0; p < 2; p++) { sum[n][p] = 0.f; sq[n][p] = 0.f; }

        #pragma unroll
        for (int mt = 0; mt < 2; mt++) {
            int j0 = jg * 32 + mt * 16 + g;
            float b0 = sbp[j0], b1 = sbp[j0 + 8];
            #pragma unroll
            for (int n = 0; n < 5; n++) {
                d[mt][n][0] += b0;
                d[mt][n][1] += b0;
                d[mt][n][2] += b1;
                d[mt][n][3] += b1;
                sum[n][0] += d[mt][n][0] + d[mt][n][2];
                sum[n][1] += d[mt][n][1] + d[mt][n][3];
                sq[n][0] = fmaf(d[mt][n][0], d[mt][n][0],
                           fmaf(d[mt][n][2], d[mt][n][2], sq[n][0]));
                sq[n][1] = fmaf(d[mt][n][1], d[mt][n][1],
                           fmaf(d[mt][n][3], d[mt][n][3], sq[n][1]));
            }
        }
        #pragma unroll
        for (int off = 4; off <= 16; off <<= 1) {
            #pragma unroll
            for (int n = 0; n < 5; n++) {
                #pragma unroll
                for (int p = 0; p < 2; p++) {
                    sum[n][p] += __shfl_xor_sync(0xffffffffu, sum[n][p], off);
                    sq[n][p]  += __shfl_xor_sync(0xffffffffu, sq[n][p],  off);
                }
            }
        }
        if (lane < 4) {   // writer lane == t4, g==0 ; transposed layout
            #pragma unroll
            for (int n = 0; n < 5; n++)
                #pragma unroll
                for (int p = 0; p < 2; p++)
                    red[(sb + n * 8 + 2 * lane + p) * 4 + jg] =
                        make_float2(sum[n][p], sq[n][p]);
        }
        __syncthreads();

        // ---- BATCHED mu/rs (rsqrtf ILP), combine via LDS.128 ----
        float mu[5][2], rs[5][2];
        #pragma unroll
        for (int n = 0; n < 5; n++) {
            #pragma unroll
            for (int p = 0; p < 2; p++) {
                int col = sb + n * 8 + 2 * t4 + p;
                const float4* q = (const float4*)(red + col * 4);
                float4 a = q[0], b = q[1];
                float sv = (a.x + a.z) + (b.x + b.z);
                float qv = (a.y + a.w) + (b.y + b.w);
                float m_ = sv * (1.0f / 128.0f);
                mu[n][p] = m_;
                rs[n][p] = rsqrtf(qv * (1.0f / 128.0f) - m_ * m_);
            }
        }

        // ---- apply LN + residual (x from fp16 tile), store ----
        const int tb = t * TS;
        #pragma unroll
        for (int mt = 0; mt < 2; mt++) {
            int j0 = jg * 32 + mt * 16 + g;
            int j1 = j0 + 8;
            float g0 = sgp[j0], e0 = sbt[j0];
            float g1 = sgp[j1], e1 = sbt[j1];
            #pragma unroll
            for (int n = 0; n < 5; n++) {
                int sl = sb + n * 8 + 2 * t4;
                __half2 x0 = *(__half2*)(xh + j0 * XPITCH + sl);
                __half2 x1 = *(__half2*)(xh + j1 * XPITCH + sl);
                float2 o0, o1;
                o0.x = (d[mt][n][0] - mu[n][0]) * rs[n][0] * g0 + e0 +
                       __half2float(x0.x);
                o0.y = (d[mt][n][1] - mu[n][1]) * rs[n][1] * g0 + e0 +
                       __half2float(x0.y);
                o1.x = (d[mt][n][2] - mu[n][0]) * rs[n][0] * g1 + e1 +
                       __half2float(x1.x);
                o1.y = (d[mt][n][3] - mu[n][1]) * rs[n][1] * g1 + e1 +
                       __half2float(x1.y);
                *(float2*)(ob + (size_t)j0 * S + tb + sl) = o0;
                *(float2*)(ob + (size_t)j1 * S + tb + sl) = o1;
            }
        }
    }
}

extern "C" void kernel_launch(void* const* d_in, const int* in_sizes, int n_in,
                              void* d_out, int out_size) {
    // metadata order: x, Wq, bq, gq, betaq, Wk, bk, gk, betak, Wp, bp, gp, betap
    const float* x     = (const float*)d_in[0];
    const float* Wp    = (const float*)d_in[9];
    const float* bp    = (const float*)d_in[10];
    const float* gp    = (const float*)d_in[11];
    const float* betap = (const float*)d_in[12];
    float* out = (float*)d_out;

    const int BO = in_sizes[0] / (C * S);   // 1024

    cudaFuncSetAttribute(ca_mma, cudaFuncAttributeMaxDynamicSharedMemorySize,
                         SM_TOTAL);

    wprep<<<8, 256>>>(Wp);
    ca_mma<<<BO, THREADS, SM_TOTAL>>>(x, bp, gp, betap, out);
}

// round 16
// speedup vs baseline: 1.3481x; 1.1778x over previous
#include <cuda_runtime.h>
#include <cuda_fp16.h>
#include <cstdint>

// channel_attention collapses to: out = LN_c(Wp @ x + bp)*gp + betap + x
// (softmax row-sum == 1 makes the q/k/attention branch an identity).
//
// Round-12 math/epilogue, half-width CTA: 128 threads = 4 warps (4 j-groups
// x full 40-s strip), grid = bo x 2 s-halves, 4 CTAs/SM. Same per-column
// traffic; finer barrier scope + more independent CTAs to hide latency.
//
// HMMA m16n8k16 fp16 GEMM (y = Wh*Xh; rel_err ~2.5e-4 incl. fp16 residual).
// X: LDG float4 -> fp16 regs -> STS, double-buffered XH; prefetch overlaps
// MMA. A streamed from L1-hot pre-packed global image.

#define C        128
#define S        400
#define TS       40                     // s per tile (CTA strip)
#define NTILES   5                      // 5 x 40 = 200 s per CTA
#define THREADS  128
#define XPITCH   56                     // fp16 pitch: 112B row = 28-word
                                        // stride -> 8 ldsm rows hit distinct
                                        // banks (28r mod 32 all distinct)
#define KSTEP    (16 * XPITCH * 2)

#define SM_XH0   0                      // 128*56*2 = 14336
#define SM_XH1   14336
#define SM_BP    28672
#define SM_GP    (SM_BP + 512)
#define SM_BT    (SM_GP + 512)
#define SM_RED   (SM_BT + 512)          // float2[4 jg][40] = 1280
#define SM_TOTAL (SM_RED + 1280)        // 31488 B -> 4 CTAs/SM (reg-capped)

// Wh fragments in mma order: [mt 8][ks 8][lane 32] x uint4 (16 KB, L1-hot)
__device__ __align__(16) uint32_t Whf[8 * 8 * 32 * 4];

__device__ __forceinline__ uint32_t smem_u32(const void* p) {
    uint32_t a;
    asm("{ .reg .u64 t; cvta.to.shared.u64 t, %1; cvt.u32.u64 %0, t; }"
        : "=r"(a) : "l"(p));
    return a;
}
__device__ __forceinline__ void ldsm4t(uint32_t* r, uint32_t addr) {
    asm volatile("ldmatrix.sync.aligned.m8n8.x4.trans.shared.b16 {%0,%1,%2,%3}, [%4];"
                 : "=r"(r[0]), "=r"(r[1]), "=r"(r[2]), "=r"(r[3]) : "r"(addr));
}
__device__ __forceinline__ void ldsm2t(uint32_t* r, uint32_t addr) {
    asm volatile("ldmatrix.sync.aligned.m8n8.x2.trans.shared.b16 {%0,%1}, [%2];"
                 : "=r"(r[0]), "=r"(r[1]) : "r"(addr));
}
__device__ __forceinline__ void mma16816(float d[4], uint4 a,
                                         uint32_t b0, uint32_t b1) {
    asm volatile(
        "mma.sync.aligned.m16n8k16.row.col.f32.f16.f16.f32 "
        "{%0,%1,%2,%3}, {%4,%5,%6,%7}, {%8,%9}, {%0,%1,%2,%3};"
        : "+f"(d[0]), "+f"(d[1]), "+f"(d[2]), "+f"(d[3])
        : "r"(a.x), "r"(a.y), "r"(a.z), "r"(a.w), "r"(b0), "r"(b1));
}
__device__ __forceinline__ uint32_t pk_h2(float a, float b) {
    __half2 h = __floats2half2_rn(a, b);    // low = a
    return *reinterpret_cast<uint32_t*>(&h);
}

// pack Wh into mma A-fragment order (mt = 16-j tile index 0..7)
__global__ void wprep(const float* __restrict__ Wp) {
    int idx  = blockIdx.x * 256 + threadIdx.x;   // (mt*8+ks)*32+lane
    int lane = idx & 31;
    int ks   = (idx >> 5) & 7;
    int mt   = idx >> 8;
    uint32_t h4[4];
    #pragma unroll
    for (int r = 0; r < 4; r++) {
        int j = mt * 16 + (r & 1) * 8 + (lane >> 2);
        int c = ks * 16 + (r >> 1) * 8 + 2 * (lane & 3);
        h4[r] = pk_h2(Wp[j * C + c], Wp[j * C + c + 1]);
    }
    ((uint4*)Whf)[idx] = make_uint4(h4[0], h4[1], h4[2], h4[3]);
}

extern __shared__ char smem[];

// load one 40-s tile strip into fp16 register chunks (10 x uint2 / thread)
__device__ __forceinline__ void load_pre(uint2 pre[10], int tid,
                                         const float* __restrict__ xt) {
    #pragma unroll
    for (int k = 0; k < 10; k++) {
        int idx = tid + k * THREADS;
        int c = idx / 10;                // row (c), 10 float4-chunks per row
        int q = (idx % 10) * 4;          // s offset
        float4 v = __ldg((const float4*)(xt + (size_t)c * S + q));
        pre[k] = make_uint2(pk_h2(v.x, v.y), pk_h2(v.z, v.w));
    }
}

__global__ __launch_bounds__(THREADS, 4)
void ca_mma(const float* __restrict__ x,
            const float* __restrict__ bp,
            const float* __restrict__ gp,
            const float* __restrict__ betap,
            float* __restrict__ out) {
    const int tid  = threadIdx.x;
    const int jg   = tid >> 5;           // warp = j-group 0..3 (32 j each)
    const int lane = tid & 31;
    const int g    = lane >> 2;
    const int t4   = lane & 3;
    const int bo   = blockIdx.x >> 1;
    const int soff = (blockIdx.x & 1) * 200;   // s-half base

    const float* xg = x   + (size_t)bo * C * S + soff;
    float*       ob = out + (size_t)bo * C * S + soff;

    float*  sbp = (float*)(smem + SM_BP);
    float*  sgp = (float*)(smem + SM_GP);
    float*  sbt = (float*)(smem + SM_BT);
    float2* red = (float2*)(smem + SM_RED);   // [jg][40]

    sbp[tid] = bp[tid];
    sgp[tid] = gp[tid];
    sbt[tid] = betap[tid];

    const int lr = lane & 15;
    const int lc = (lane >> 4) << 3;
    const uint32_t s0   = smem_u32(smem);
    const uint32_t xrel = (uint32_t)((lr * XPITCH + lc) * 2);
    const uint4* wh = (const uint4*)Whf;

    // prefetch+convert tile 0 into registers
    uint2 pre[10];
    load_pre(pre, tid, xg);

    for (int t = 0; t < NTILES; t++) {
        const uint32_t xhb = (t & 1) ? SM_XH1 : SM_XH0;
        __half* xh = (__half*)(smem + xhb);

        __syncthreads();   // XH(t&1) readers (tile t-2) are done
        // store converted tile, then issue next tile's loads
        #pragma unroll
        for (int k = 0; k < 10; k++) {
            int idx = tid + k * THREADS;
            int c = idx / 10;
            int q = (idx % 10) * 4;
            *(uint2*)(xh + c * XPITCH + q) = pre[k];
        }
        if (t + 1 < NTILES)
            load_pre(pre, tid, xg + (t + 1) * TS);
        __syncthreads();

        // ---- MMA: A streamed from global (L1-hot), B via ldsm ----
        const uint32_t aXh = s0 + xhb + xrel;
        float d[2][5][4];
        #pragma unroll
        for (int mt = 0; mt < 2; mt++)
            #pragma unroll
            for (int n = 0; n < 5; n++)
                #pragma unroll
                for (int i = 0; i < 4; i++) d[mt][n][i] = 0.0f;

        #pragma unroll
        for (int ks = 0; ks < 8; ks++) {
            uint4 ah0 = __ldg(wh + ((2 * jg)     * 8 + ks) * 32 + lane);
            uint4 ah1 = __ldg(wh + ((2 * jg + 1) * 8 + ks) * 32 + lane);
            uint32_t bh[10];
            ldsm4t(bh,     aXh + ks * KSTEP);
            ldsm4t(bh + 4, aXh + ks * KSTEP + 32);
            ldsm2t(bh + 8, aXh + ks * KSTEP + 64);
            #pragma unroll
            for (int n = 0; n < 5; n++) {
                mma16816(d[0][n], ah0, bh[2 * n], bh[2 * n + 1]);
                mma16816(d[1][n], ah1, bh[2 * n], bh[2 * n + 1]);
            }
        }

        // ---- epilogue: +bias, LN stats over 32 j in-warp ----
        float sum[5][2], sq[5][2];
        #pragma unroll
        for (int n = 0; n < 5; n++)
            #pragma unroll
            for (int p = 0; p < 2; p++) { sum[n][p] = 0.f; sq[n][p] = 0.f; }

        #pragma unroll
        for (int mt = 0; mt < 2; mt++) {
            int j0 = jg * 32 + mt * 16 + g;
            float b0 = sbp[j0], b1 = sbp[j0 + 8];
            #pragma unroll
            for (int n = 0; n < 5; n++) {
                d[mt][n][0] += b0;
                d[mt][n][1] += b0;
                d[mt][n][2] += b1;
                d[mt][n][3] += b1;
                sum[n][0] += d[mt][n][0] + d[mt][n][2];
                sum[n][1] += d[mt][n][1] + d[mt][n][3];
                sq[n][0] = fmaf(d[mt][n][0], d[mt][n][0],
                           fmaf(d[mt][n][2], d[mt][n][2], sq[n][0]));
                sq[n][1] = fmaf(d[mt][n][1], d[mt][n][1],
                           fmaf(d[mt][n][3], d[mt][n][3], sq[n][1]));
            }
        }
        #pragma unroll
        for (int off = 4; off <= 16; off <<= 1) {
            #pragma unroll
            for (int n = 0; n < 5; n++) {
                #pragma unroll
                for (int p = 0; p < 2; p++) {
                    sum[n][p] += __shfl_xor_sync(0xffffffffu, sum[n][p], off);
                    sq[n][p]  += __shfl_xor_sync(0xffffffffu, sq[n][p],  off);
                }
            }
        }
        if (lane < 4) {   // writer lane == t4, g==0
            #pragma unroll
            for (int n = 0; n < 5; n++)
                #pragma unroll
                for (int p = 0; p < 2; p++)
                    red[jg * TS + n * 8 + 2 * lane + p] =
                        make_float2(sum[n][p], sq[n][p]);
        }
        __syncthreads();

        // ---- batched mu/rs (r12 style) ----
        float mu[5][2], rs[5][2];
        #pragma unroll
        for (int n = 0; n < 5; n++) {
            #pragma unroll
            for (int p = 0; p < 2; p++) {
                int col = n * 8 + 2 * t4 + p;
                float sv = 0.f, qv = 0.f;
                #pragma unroll
                for (int jj = 0; jj < 4; jj++) {
                    float2 r = red[jj * TS + col];
                    sv += r.x;
                    qv += r.y;
                }
                float m_  = sv * (1.0f / 128.0f);
                float var = qv * (1.0f / 128.0f) - m_ * m_;
                mu[n][p] = m_;
                rs[n][p] = rsqrtf(var + 1e-5f);
            }
        }

        // ---- apply LN + residual (x from fp16 tile), store ----
        const int tb = t * TS;
        #pragma unroll
        for (int mt = 0; mt < 2; mt++) {
            int j0 = jg * 32 + mt * 16 + g;
            int j1 = j0 + 8;
            float g0 = sgp[j0], e0 = sbt[j0];
            float g1 = sgp[j1], e1 = sbt[j1];
            #pragma unroll
            for (int n = 0; n < 5; n++) {
                int sl = n * 8 + 2 * t4;
                __half2 x0 = *(__half2*)(xh + j0 * XPITCH + sl);
                __half2 x1 = *(__half2*)(xh + j1 * XPITCH + sl);
                float2 o0, o1;
                o0.x = (d[mt][n][0] - mu[n][0]) * rs[n][0] * g0 + e0 +
                       __half2float(x0.x);
                o0.y = (d[mt][n][1] - mu[n][1]) * rs[n][1] * g0 + e0 +
                       __half2float(x0.y);
                o1.x = (d[mt][n][2] - mu[n][0]) * rs[n][0] * g1 + e1 +
                       __half2float(x1.x);
                o1.y = (d[mt][n][3] - mu[n][1]) * rs[n][1] * g1 + e1 +
                       __half2float(x1.y);
                *(float2*)(ob + (size_t)j0 * S + tb + sl) = o0;
                *(float2*)(ob + (size_t)j1 * S + tb + sl) = o1;
            }
        }
    }
}

extern "C" void kernel_launch(void* const* d_in, const int* in_sizes, int n_in,
                              void* d_out, int out_size) {
    // metadata order: x, Wq, bq, gq, betaq, Wk, bk, gk, betak, Wp, bp, gp, betap
    const float* x     = (const float*)d_in[0];
    const float* Wp    = (const float*)d_in[9];
    const float* bp    = (const float*)d_in[10];
    const float* gp    = (const float*)d_in[11];
    const float* betap = (const float*)d_in[12];
    float* out = (float*)d_out;

    const int BO = in_sizes[0] / (C * S);   // 1024

    cudaFuncSetAttribute(ca_mma, cudaFuncAttributeMaxDynamicSharedMemorySize,
                         SM_TOTAL);

    wprep<<<8, 256>>>(Wp);
    ca_mma<<<BO * 2, THREADS, SM_TOTAL>>>(x, bp, gp, betap, out);
}